// round 16
// baseline (speedup 1.0000x reference)
#include <cuda_runtime.h>
#include <cuda_fp16.h>
#include <cstdint>
#include <cstddef>

#define NB 4
#define NT 8
#define HWPX 4096
#define NFRM 32          // NB*NT
#define WHALF 18432      // halves per (layer,half) weight slice: 9*64*32
#define NBLK 256u        // persistent grid size (32*2*4)

// ---------------- device scratch ----------------
__device__ __half g_xf16 [(size_t)NFRM * HWPX * 32];   // layer-0 conv input (BN folded, fp16, swizzled)
__device__ __half g_x2f16[(size_t)NFRM * HWPX * 32];   // layer-1 conv input (BN folded, fp16, swizzled)
__device__ __half g_w16  [2 * 2 * 9 * 64 * 32];        // input kernels  [l][half][tap][ell64][cin32]
__device__ __half g_rw16 [2 * 2 * 9 * 64 * 32];        // recurrent kernels, same layout
__device__ __half g_h16  [(size_t)NB * HWPX * 32];     // hidden state fp16 swizzled
__device__ float  g_l0   [(size_t)NFRM * HWPX * 32];   // layer-0 output fp32 (residual source)
__device__ unsigned g_bar;                             // persistent-kernel grid barrier

__device__ __forceinline__ float hsig(float x) { return __saturatef(fmaf(x, 0.2f, 0.5f)); }

__device__ __forceinline__ void ldsm4(unsigned* r, unsigned saddr) {
    asm volatile("ldmatrix.sync.aligned.m8n8.x4.shared.b16 {%0,%1,%2,%3}, [%4];\n"
        : "=r"(r[0]), "=r"(r[1]), "=r"(r[2]), "=r"(r[3]) : "r"(saddr));
}
__device__ __forceinline__ void mma16816(float* d, const unsigned* a, const unsigned* b) {
    asm volatile("mma.sync.aligned.m16n8k16.row.col.f32.f16.f16.f32 "
        "{%0,%1,%2,%3}, {%4,%5,%6,%7}, {%8,%9}, {%0,%1,%2,%3};\n"
        : "+f"(d[0]), "+f"(d[1]), "+f"(d[2]), "+f"(d[3])
        : "r"(a[0]), "r"(a[1]), "r"(a[2]), "r"(a[3]), "r"(b[0]), "r"(b[1]));
}

// grid-wide barrier. Release via red.release (orders prior stores to L2 without a
// full membar/L1-flush); acquire via ld.acquire polling. Valid here because ALL
// mutated global data crossing the barrier is consumed via L2 paths only
// (cp.async staging, __ldcg residual reads) -- no L1-cached re-reads of mutated data.
__device__ __forceinline__ void grid_sync(unsigned target) {
    __syncthreads();
    if (threadIdx.x == 0) {
        asm volatile("red.release.gpu.global.add.u32 [%0], %1;"
                     :: "l"(&g_bar), "r"(1u) : "memory");
        unsigned v;
        for (;;) {
            asm volatile("ld.acquire.gpu.global.u32 %0, [%1];"
                         : "=r"(v) : "l"(&g_bar) : "memory");
            if (v >= target) break;
            __nanosleep(64);
        }
    }
    __syncthreads();
}

// ---------------- merged prep: bar reset + weights + layer-0 input ----------
// blocks [0,576): weight transform; blocks [576, 4672): input BN fold.
__global__ void prep_all(const float* __restrict__ x, const float* __restrict__ gma,
                         const float* __restrict__ bta, const float* __restrict__ mu,
                         const float* __restrict__ var,
                         const float* __restrict__ ker, const float* __restrict__ rker)
{
    const int bid = blockIdx.x;
    const int tid = threadIdx.x;
    if (bid == 0 && tid == 0) g_bar = 0u;

    if (bid < 576) {
        int idx = bid * 256 + tid;
        if (idx >= 2 * 73728) return;
        int tsel = idx >= 73728;
        int rem  = idx - tsel * 73728;
        const float* src = tsel ? rker : ker;
        __half* dst = tsel ? g_rw16 : g_w16;
        int l   = rem / 36864;
        int r2  = rem - l * 36864;
        int tap = r2 >> 12;
        int r3  = r2 & 4095;
        int cin = r3 >> 7;
        int oc  = r3 & 127;
        int g   = oc >> 5;
        int f   = oc & 31;
        int half = f >> 4;
        int nw   = (f >> 3) & 1;
        int ell  = nw * 32 + g * 8 + (f & 7);
        int sch  = (cin >> 3) ^ ((ell >> 1) & 3);
        dst[(size_t)(l * 2 + half) * WHALF + tap * 2048 + ell * 32 + sch * 8 + (cin & 7)]
            = __float2half(src[rem]);
    } else {
        int idx = (bid - 576) * 256 + tid;       // 32*4096*8 threads
        int p   = idx >> 3;
        int c4  = (idx & 7) << 2;
        int xcol = p & 63;
        float4 v = *reinterpret_cast<const float4*>(x + (size_t)p * 32 + c4);
        float sc[4], bb[4];
        #pragma unroll
        for (int i = 0; i < 4; ++i) {
            float g = __ldg(gma + c4 + i);
            sc[i] = g * rsqrtf(__ldg(var + c4 + i) + 1e-3f);
            bb[i] = __ldg(bta + c4 + i) - __ldg(mu + c4 + i) * sc[i];
        }
        __half2 h0 = __floats2half2_rn(fmaf(v.x, sc[0], bb[0]), fmaf(v.y, sc[1], bb[1]));
        __half2 h1 = __floats2half2_rn(fmaf(v.z, sc[2], bb[2]), fmaf(v.w, sc[3], bb[3]));
        int sch = (c4 >> 3) ^ (((xcol + 1) >> 1) & 3);
        __half* d = g_xf16 + (size_t)p * 32 + sch * 8 + (c4 & 7);
        *reinterpret_cast<__half2*>(d)     = h0;
        *reinterpret_cast<__half2*>(d + 2) = h1;
    }
}

// ---------------- shared building blocks ----------------
// async tile stage: issues cp.async (zero-fill for halo), caller commits/waits
__device__ __forceinline__ void stage_tile_async(const __half* __restrict__ inF,
                                                 __half* __restrict__ in_s,
                                                 int tid, int y0) {
    for (int idx = tid; idx < 1056; idx += 256) {
        int r4 = idx / 264;
        int rem = idx - r4 * 264;
        int xp = rem >> 2;
        int ch = rem & 3;
        int yy = y0 - 1 + r4;
        bool v = (xp >= 1 && xp <= 64 && yy >= 0 && yy < 64);
        const __half* gsrc = v ? inF + ((size_t)(yy * 64 + xp - 1) << 5) + ch * 8
                               : inF;
        unsigned saddr = (unsigned)__cvta_generic_to_shared(
            in_s + (size_t)(r4 * 66 + xp) * 32 + ch * 8);
        int sz = v ? 16 : 0;
        asm volatile("cp.async.cg.shared.global [%0], [%1], 16, %2;\n"
                     :: "r"(saddr), "l"(gsrc), "r"(sz));
    }
}
__device__ __forceinline__ void cpasync_commit() {
    asm volatile("cp.async.commit_group;\n");
}
__device__ __forceinline__ void cpasync_wait0() {
    asm volatile("cp.async.wait_group 0;\n");
}
__device__ __forceinline__ void cpasync_wait1() {
    asm volatile("cp.async.wait_group 1;\n");
}

__device__ __forceinline__ void conv_mainloop(unsigned in_base, unsigned b_base,
                                              int mwarp, int nw, int lane,
                                              float acc[2][4][4]) {
    const int ylw = mwarp >> 1;
    const int xbw = (mwarp & 1) * 32;
    const int moff  = lane & 15;
    const int kselA = lane >> 4;
    const int noffB = (lane & 7) | ((lane >> 1) & 8);
    const int kselB = (lane >> 3) & 1;

    #pragma unroll
    for (int tap = 0; tap < 9; ++tap) {
        const int dy = tap / 3, dx = tap % 3;
        const int yl = ylw + dy;
        #pragma unroll
        for (int h = 0; h < 2; ++h) {
            unsigned a[2][4];
            #pragma unroll
            for (int mt = 0; mt < 2; ++mt) {
                int xq = xbw + mt * 16 + moff + dx;
                int ch = (h << 1) | kselA;
                int sch = ch ^ ((xq >> 1) & 3);
                unsigned addr = in_base + (unsigned)((((yl * 66 + xq) << 5) + (sch << 3)) << 1);
                ldsm4(a[mt], addr);
            }
            unsigned bfrag[4][2];
            #pragma unroll
            for (int p = 0; p < 2; ++p) {
                int n = nw * 32 + p * 16 + noffB;
                int kc = (h << 1) | kselB;
                int sch = kc ^ ((n >> 1) & 3);
                unsigned addr = b_base + (unsigned)(((((tap * 64 + n) << 5)) + (sch << 3)) << 1);
                unsigned r[4];
                ldsm4(r, addr);
                bfrag[2 * p][0] = r[0]; bfrag[2 * p][1] = r[1];
                bfrag[2 * p + 1][0] = r[2]; bfrag[2 * p + 1][1] = r[3];
            }
            #pragma unroll
            for (int mt = 0; mt < 2; ++mt)
                #pragma unroll
                for (int j = 0; j < 4; ++j)
                    mma16816(acc[mt][j], a[mt], bfrag[j]);
        }
    }
}

// ---------------- fused persistent 2-layer ConvLSTM ------------------------
// ONE launch = both layers x 8 timesteps. Per layer: z(t) = conv_W(x_t) +
// conv_U(h_{t-1}) + bias in one fp32 MMA chain; x(t+1) prefetched before the
// grid barrier; h staged via cp.async overlapped with the x mainloop;
// residual reads prefetched. Layer transition = one grid_sync + in-kernel
// weight reload. 15 grid barriers total.
// smem: x tile 8448 | h tile 8448 | W 18432 | U 18432 halves = 107520 B.
__global__ __launch_bounds__(256, 2)
void lstm_mega(const __half* __restrict__ x1, const __half* __restrict__ x2,
               const __half* __restrict__ wall, const __half* __restrict__ uall,
               const float* __restrict__ biasall,
               __half* __restrict__ hstate,
               float* __restrict__ out0, __half* __restrict__ out16,
               float* __restrict__ outF,
               const float* __restrict__ g1, const float* __restrict__ be1,
               const float* __restrict__ mu1, const float* __restrict__ va1)
{
    extern __shared__ __half sm[];
    __half* x_s = sm;                 // 8448
    __half* h_s = sm + 8448;          // 8448
    __half* W_s = sm + 16896;         // 18432
    __half* U_s = sm + 35328;         // 18432

    const int tid  = threadIdx.x;
    const int lane = tid & 31, w = tid >> 5;
    const int mwarp = w >> 1, nw = w & 1;
    const int gid = lane >> 2, tig = lane & 3;
    const int y0 = blockIdx.x * 2;
    const int nh = blockIdx.y;
    const int b  = blockIdx.z;

    const int f = nh * 16 + nw * 8 + tig * 2;

    unsigned x_base = (unsigned)__cvta_generic_to_shared(x_s);
    unsigned h_base = (unsigned)__cvta_generic_to_shared(h_s);
    unsigned wW = (unsigned)__cvta_generic_to_shared(W_s);
    unsigned wU = (unsigned)__cvta_generic_to_shared(U_s);

    unsigned barcnt = 0;

    for (int l = 0; l < 2; ++l) {
        const bool isl0 = (l == 0);
        const __half* xin = isl0 ? x1 : x2;

        // kick off async stage of x frame t=0 for this layer
        stage_tile_async(xin + (size_t)(b * NT) * (HWPX * 32), x_s, tid, y0);
        cpasync_commit();

        // stage this layer's weight slices (overlaps with in-flight cp.async)
        const __half* wsrc = wall + (size_t)(l * 2 + nh) * WHALF;
        const __half* usrc = uall + (size_t)(l * 2 + nh) * WHALF;
        for (int idx = tid; idx < 2304; idx += 256) {
            *reinterpret_cast<uint4*>(W_s + idx * 8) =
                *reinterpret_cast<const uint4*>(wsrc + idx * 8);
            *reinterpret_cast<uint4*>(U_s + idx * 8) =
                *reinterpret_cast<const uint4*>(usrc + idx * 8);
        }

        const float* bias = biasall + l * 128;
        float bz[4][2];
        #pragma unroll
        for (int g = 0; g < 4; ++g) {
            float2 bv = *reinterpret_cast<const float2*>(bias + g * 32 + f);
            bz[g][0] = bv.x; bz[g][1] = bv.y;
        }
        float sbn[2], bbn[2];
        if (isl0) {
            #pragma unroll
            for (int c2 = 0; c2 < 2; ++c2) {
                float g = __ldg(g1 + f + c2);
                float s = g * rsqrtf(__ldg(va1 + f + c2) + 1e-3f);
                sbn[c2] = s;
                bbn[c2] = __ldg(be1 + f + c2) - __ldg(mu1 + f + c2) * s;
            }
        }

        float2 creg[2][2];
        #pragma unroll
        for (int mt = 0; mt < 2; ++mt)
            #pragma unroll
            for (int r = 0; r < 2; ++r) { creg[mt][r].x = 0.f; creg[mt][r].y = 0.f; }

        for (int t = 0; t < NT; ++t) {
            const int frame = b * NT + t;

            float acc[2][4][4];
            #pragma unroll
            for (int mt = 0; mt < 2; ++mt)
                #pragma unroll
                for (int j = 0; j < 4; ++j)
                    #pragma unroll
                    for (int q = 0; q < 4; ++q) acc[mt][j][q] = 0.f;

            if (t > 0) {
                // h tile streams in while the x mainloop runs
                stage_tile_async(hstate + (size_t)b * (HWPX * 32), h_s, tid, y0);
                cpasync_commit();
                cpasync_wait1();          // x group (older) complete
            } else {
                cpasync_wait0();
            }

            // prefetch residual reads for this step (layer 1 only)
            float2 rpre[2][2];
            if (!isl0) {
                #pragma unroll
                for (int mt = 0; mt < 2; ++mt)
                    #pragma unroll
                    for (int r = 0; r < 2; ++r) {
                        int m = mwarp * 32 + mt * 16 + r * 8 + gid;
                        int pix = (y0 + (m >> 6)) * 64 + (m & 63);
                        rpre[mt][r] = __ldcg(reinterpret_cast<const float2*>(
                            out0 + ((size_t)frame * HWPX + pix) * 32 + f));
                    }
            }

            __syncthreads();              // x_s (and W/U on t=0) visible block-wide
            conv_mainloop(x_base, wW, mwarp, nw, lane, acc);
            if (t > 0) {
                cpasync_wait0();          // h group complete
                __syncthreads();          // h_s visible block-wide
                conv_mainloop(h_base, wU, mwarp, nw, lane, acc);
            }

            #pragma unroll
            for (int mt = 0; mt < 2; ++mt) {
                #pragma unroll
                for (int r = 0; r < 2; ++r) {
                    int m = mwarp * 32 + mt * 16 + r * 8 + gid;
                    int xcol = m & 63;
                    int pix = (y0 + (m >> 6)) * 64 + xcol;
                    float z4[4][2];
                    #pragma unroll
                    for (int g = 0; g < 4; ++g) {
                        z4[g][0] = acc[mt][g][2 * r]     + bz[g][0];
                        z4[g][1] = acc[mt][g][2 * r + 1] + bz[g][1];
                    }
                    float2 cp = creg[mt][r];
                    float2 cn, hv;
                    cn.x = hsig(z4[1][0]) * cp.x + hsig(z4[0][0]) * tanhf(z4[2][0]);
                    cn.y = hsig(z4[1][1]) * cp.y + hsig(z4[0][1]) * tanhf(z4[2][1]);
                    hv.x = hsig(z4[3][0]) * tanhf(cn.x);
                    hv.y = hsig(z4[3][1]) * tanhf(cn.y);
                    creg[mt][r] = cn;
                    int sch = (f >> 3) ^ (((xcol + 1) >> 1) & 3);
                    if (t < NT - 1)
                        *reinterpret_cast<__half2*>(hstate + ((size_t)b * HWPX + pix) * 32
                                                    + sch * 8 + (f & 7)) =
                            __floats2half2_rn(hv.x, hv.y);
                    size_t oo = ((size_t)frame * HWPX + pix) * 32 + f;
                    if (isl0) {
                        *reinterpret_cast<float2*>(out0 + oo) = hv;
                        *reinterpret_cast<__half2*>(out16 + ((size_t)frame * HWPX + pix) * 32
                                                    + sch * 8 + (f & 7)) =
                            __floats2half2_rn(fmaf(hv.x, sbn[0], bbn[0]),
                                              fmaf(hv.y, sbn[1], bbn[1]));
                    } else {
                        float2 ov; ov.x = hv.x + rpre[mt][r].x; ov.y = hv.y + rpre[mt][r].y;
                        *reinterpret_cast<float2*>(outF + oo) = ov;
                    }
                }
            }

            if (t < NT - 1) {
                __syncthreads();     // all warps done reading x_s
                stage_tile_async(xin + (size_t)(frame + 1) * (HWPX * 32), x_s, tid, y0);
                cpasync_commit();    // overlaps with the barrier spin below
                grid_sync(NBLK * (++barcnt));
            }
        }

        // layer transition: all layer-0 outputs (x2, l0) released before layer 1
        if (l == 0) grid_sync(NBLK * (++barcnt));
    }
}

// ---------------------------------------------------------------------------
extern "C" void kernel_launch(void* const* d_in, const int* in_sizes, int n_in,
                              void* d_out, int out_size)
{
    (void)in_sizes; (void)n_in; (void)out_size;
    const float* x    = (const float*)d_in[0];
    const float* gma  = (const float*)d_in[1];
    const float* bta  = (const float*)d_in[2];
    const float* mu   = (const float*)d_in[3];
    const float* var  = (const float*)d_in[4];
    const float* ker  = (const float*)d_in[5];
    const float* rker = (const float*)d_in[6];
    const float* bias = (const float*)d_in[7];

    __half *xf16, *x2f16, *w16, *rw16, *h16;
    float *l0;
    cudaGetSymbolAddress((void**)&xf16,  g_xf16);
    cudaGetSymbolAddress((void**)&x2f16, g_x2f16);
    cudaGetSymbolAddress((void**)&w16,   g_w16);
    cudaGetSymbolAddress((void**)&rw16,  g_rw16);
    cudaGetSymbolAddress((void**)&h16,   g_h16);
    cudaGetSymbolAddress((void**)&l0,    g_l0);

    const size_t SMEM = (2 * 8448 + 2 * 18432) * sizeof(__half);   // 107520 B
    cudaFuncSetAttribute((const void*)lstm_mega,
                         cudaFuncAttributeMaxDynamicSharedMemorySize, (int)SMEM);

    prep_all<<<4672, 256>>>(x, gma, bta, mu, var, ker, rker);

    lstm_mega<<<dim3(32, 2, NB), 256, SMEM>>>(
        xf16, x2f16, w16, rw16, bias, h16, l0, x2f16, (float*)d_out,
        gma + 32, bta + 32, mu + 32, var + 32);
}

// round 17
// speedup vs baseline: 1.5116x; 1.5116x over previous
#include <cuda_runtime.h>
#include <cuda_fp16.h>
#include <cstdint>
#include <cstddef>

#define NB 4
#define NT 8
#define HWPX 4096
#define NFRM 32          // NB*NT
#define WHALF 18432      // halves per (layer,half) weight slice: 9*64*32
#define BBLK 64u         // blocks per batch element (32*2)

// ---------------- device scratch ----------------
__device__ __half g_xf16 [(size_t)NFRM * HWPX * 32];   // layer-0 conv input (BN folded, fp16, swizzled)
__device__ __half g_x2f16[(size_t)NFRM * HWPX * 32];   // layer-1 conv input (BN folded, fp16, swizzled)
__device__ __half g_w16  [2 * 2 * 9 * 64 * 32];        // input kernels  [l][half][tap][ell64][cin32]
__device__ __half g_rw16 [2 * 2 * 9 * 64 * 32];        // recurrent kernels, same layout
__device__ __half g_h16  [(size_t)NB * HWPX * 32];     // hidden state fp16 swizzled
__device__ float  g_l0   [(size_t)NFRM * HWPX * 32];   // layer-0 output fp32 (residual source)
__device__ unsigned g_barb[NB * 32];                   // per-b barrier counters, 128B apart

__device__ __forceinline__ float hsig(float x) { return __saturatef(fmaf(x, 0.2f, 0.5f)); }

__device__ __forceinline__ void ldsm4(unsigned* r, unsigned saddr) {
    asm volatile("ldmatrix.sync.aligned.m8n8.x4.shared.b16 {%0,%1,%2,%3}, [%4];\n"
        : "=r"(r[0]), "=r"(r[1]), "=r"(r[2]), "=r"(r[3]) : "r"(saddr));
}
__device__ __forceinline__ void mma16816(float* d, const unsigned* a, const unsigned* b) {
    asm volatile("mma.sync.aligned.m16n8k16.row.col.f32.f16.f16.f32 "
        "{%0,%1,%2,%3}, {%4,%5,%6,%7}, {%8,%9}, {%0,%1,%2,%3};\n"
        : "+f"(d[0]), "+f"(d[1]), "+f"(d[2]), "+f"(d[3])
        : "r"(a[0]), "r"(a[1]), "r"(a[2]), "r"(a[3]), "r"(b[0]), "r"(b[1]));
}

// per-batch barrier (release/acquire via g_barb[b*32]). 64 participants.
// Safe: all 64 blocks of a batch element are co-resident (grid co-resident by construction).
__device__ __forceinline__ void grid_sync_b(int b, unsigned target) {
    __syncthreads();
    if (threadIdx.x == 0) {
        __threadfence();
        atomicAdd(&g_barb[b * 32], 1u);
        while (*(volatile unsigned*)&g_barb[b * 32] < target) __nanosleep(64);
        __threadfence();
    }
    __syncthreads();
}

// ---------------- merged prep: bar reset + weights + layer-0 input ----------
// blocks [0,576): weight transform; blocks [576, 4672): input BN fold.
__global__ void prep_all(const float* __restrict__ x, const float* __restrict__ gma,
                         const float* __restrict__ bta, const float* __restrict__ mu,
                         const float* __restrict__ var,
                         const float* __restrict__ ker, const float* __restrict__ rker)
{
    const int bid = blockIdx.x;
    const int tid = threadIdx.x;
    if (bid == 0 && tid < NB) g_barb[tid * 32] = 0u;

    if (bid < 576) {
        int idx = bid * 256 + tid;
        if (idx >= 2 * 73728) return;
        int tsel = idx >= 73728;
        int rem  = idx - tsel * 73728;
        const float* src = tsel ? rker : ker;
        __half* dst = tsel ? g_rw16 : g_w16;
        int l   = rem / 36864;
        int r2  = rem - l * 36864;
        int tap = r2 >> 12;
        int r3  = r2 & 4095;
        int cin = r3 >> 7;
        int oc  = r3 & 127;
        int g   = oc >> 5;
        int f   = oc & 31;
        int half = f >> 4;
        int nw   = (f >> 3) & 1;
        int ell  = nw * 32 + g * 8 + (f & 7);
        int sch  = (cin >> 3) ^ ((ell >> 1) & 3);
        dst[(size_t)(l * 2 + half) * WHALF + tap * 2048 + ell * 32 + sch * 8 + (cin & 7)]
            = __float2half(src[rem]);
    } else {
        int idx = (bid - 576) * 256 + tid;       // 32*4096*8 threads
        int p   = idx >> 3;
        int c4  = (idx & 7) << 2;
        int xcol = p & 63;
        float4 v = *reinterpret_cast<const float4*>(x + (size_t)p * 32 + c4);
        float sc[4], bb[4];
        #pragma unroll
        for (int i = 0; i < 4; ++i) {
            float g = __ldg(gma + c4 + i);
            sc[i] = g * rsqrtf(__ldg(var + c4 + i) + 1e-3f);
            bb[i] = __ldg(bta + c4 + i) - __ldg(mu + c4 + i) * sc[i];
        }
        __half2 h0 = __floats2half2_rn(fmaf(v.x, sc[0], bb[0]), fmaf(v.y, sc[1], bb[1]));
        __half2 h1 = __floats2half2_rn(fmaf(v.z, sc[2], bb[2]), fmaf(v.w, sc[3], bb[3]));
        int sch = (c4 >> 3) ^ (((xcol + 1) >> 1) & 3);
        __half* d = g_xf16 + (size_t)p * 32 + sch * 8 + (c4 & 7);
        *reinterpret_cast<__half2*>(d)     = h0;
        *reinterpret_cast<__half2*>(d + 2) = h1;
    }
}

// ---------------- shared building blocks ----------------
// async tile stage: issues cp.async (zero-fill for halo), caller commits/waits
__device__ __forceinline__ void stage_tile_async(const __half* __restrict__ inF,
                                                 __half* __restrict__ in_s,
                                                 int tid, int y0) {
    for (int idx = tid; idx < 1056; idx += 256) {
        int r4 = idx / 264;
        int rem = idx - r4 * 264;
        int xp = rem >> 2;
        int ch = rem & 3;
        int yy = y0 - 1 + r4;
        bool v = (xp >= 1 && xp <= 64 && yy >= 0 && yy < 64);
        const __half* gsrc = v ? inF + ((size_t)(yy * 64 + xp - 1) << 5) + ch * 8
                               : inF;
        unsigned saddr = (unsigned)__cvta_generic_to_shared(
            in_s + (size_t)(r4 * 66 + xp) * 32 + ch * 8);
        int sz = v ? 16 : 0;
        asm volatile("cp.async.cg.shared.global [%0], [%1], 16, %2;\n"
                     :: "r"(saddr), "l"(gsrc), "r"(sz));
    }
}
__device__ __forceinline__ void cpasync_commit() {
    asm volatile("cp.async.commit_group;\n");
}
__device__ __forceinline__ void cpasync_wait0() {
    asm volatile("cp.async.wait_group 0;\n");
}
__device__ __forceinline__ void cpasync_wait1() {
    asm volatile("cp.async.wait_group 1;\n");
}

__device__ __forceinline__ void conv_mainloop(unsigned in_base, unsigned b_base,
                                              int mwarp, int nw, int lane,
                                              float acc[2][4][4]) {
    const int ylw = mwarp >> 1;
    const int xbw = (mwarp & 1) * 32;
    const int moff  = lane & 15;
    const int kselA = lane >> 4;
    const int noffB = (lane & 7) | ((lane >> 1) & 8);
    const int kselB = (lane >> 3) & 1;

    #pragma unroll
    for (int tap = 0; tap < 9; ++tap) {
        const int dy = tap / 3, dx = tap % 3;
        const int yl = ylw + dy;
        #pragma unroll
        for (int h = 0; h < 2; ++h) {
            unsigned a[2][4];
            #pragma unroll
            for (int mt = 0; mt < 2; ++mt) {
                int xq = xbw + mt * 16 + moff + dx;
                int ch = (h << 1) | kselA;
                int sch = ch ^ ((xq >> 1) & 3);
                unsigned addr = in_base + (unsigned)((((yl * 66 + xq) << 5) + (sch << 3)) << 1);
                ldsm4(a[mt], addr);
            }
            unsigned bfrag[4][2];
            #pragma unroll
            for (int p = 0; p < 2; ++p) {
                int n = nw * 32 + p * 16 + noffB;
                int kc = (h << 1) | kselB;
                int sch = kc ^ ((n >> 1) & 3);
                unsigned addr = b_base + (unsigned)(((((tap * 64 + n) << 5)) + (sch << 3)) << 1);
                unsigned r[4];
                ldsm4(r, addr);
                bfrag[2 * p][0] = r[0]; bfrag[2 * p][1] = r[1];
                bfrag[2 * p + 1][0] = r[2]; bfrag[2 * p + 1][1] = r[3];
            }
            #pragma unroll
            for (int mt = 0; mt < 2; ++mt)
                #pragma unroll
                for (int j = 0; j < 4; ++j)
                    mma16816(acc[mt][j], a[mt], bfrag[j]);
        }
    }
}

// ---------------- fused persistent ConvLSTM layer --------------------------
// One launch = one layer: 8 timesteps, input conv + recurrent conv fused.
// z(t) = conv_W(x_t) + conv_U(h_{t-1}) + bias, one fp32 MMA accumulation chain.
// x(t+1) prefetched via cp.async before the barrier (hidden in the spin);
// h(t-1) staged via cp.async overlapped with the x-conv mainloop;
// residual reads prefetched. Barriers are PER BATCH ELEMENT (64 blocks).
// smem: x tile 8448 | h tile 8448 | W 18432 | U 18432 halves = 107520 B.
template<bool IS_L0>
__global__ __launch_bounds__(256, 2)
void lstm_fused(const __half* __restrict__ xin,
                const __half* __restrict__ wbase, const __half* __restrict__ ubase,
                const float* __restrict__ bias,
                __half* __restrict__ hstate,
                float* __restrict__ out0, __half* __restrict__ out16,
                const float* __restrict__ res, float* __restrict__ outF,
                const float* __restrict__ g1, const float* __restrict__ be1,
                const float* __restrict__ mu1, const float* __restrict__ va1,
                unsigned bar_base)
{
    extern __shared__ __half sm[];
    __half* x_s = sm;                 // 8448
    __half* h_s = sm + 8448;          // 8448
    __half* W_s = sm + 16896;         // 18432
    __half* U_s = sm + 35328;         // 18432

    const int tid  = threadIdx.x;
    const int lane = tid & 31, w = tid >> 5;
    const int mwarp = w >> 1, nw = w & 1;
    const int gid = lane >> 2, tig = lane & 3;
    const int y0 = blockIdx.x * 2;
    const int nh = blockIdx.y;
    const int b  = blockIdx.z;

    // kick off async stage of x frame t=0
    stage_tile_async(xin + (size_t)(b * NT) * (HWPX * 32), x_s, tid, y0);
    cpasync_commit();

    // stage both weight slices once (overlaps with in-flight cp.async)
    const __half* wsrc = wbase + (size_t)nh * WHALF;
    const __half* usrc = ubase + (size_t)nh * WHALF;
    for (int idx = tid; idx < 2304; idx += 256) {
        *reinterpret_cast<uint4*>(W_s + idx * 8) =
            *reinterpret_cast<const uint4*>(wsrc + idx * 8);
        *reinterpret_cast<uint4*>(U_s + idx * 8) =
            *reinterpret_cast<const uint4*>(usrc + idx * 8);
    }

    const int f = nh * 16 + nw * 8 + tig * 2;
    float bz[4][2];
    #pragma unroll
    for (int g = 0; g < 4; ++g) {
        float2 bv = *reinterpret_cast<const float2*>(bias + g * 32 + f);
        bz[g][0] = bv.x; bz[g][1] = bv.y;
    }
    float sbn[2], bbn[2];
    if (IS_L0) {
        #pragma unroll
        for (int c2 = 0; c2 < 2; ++c2) {
            float g = __ldg(g1 + f + c2);
            float s = g * rsqrtf(__ldg(va1 + f + c2) + 1e-3f);
            sbn[c2] = s;
            bbn[c2] = __ldg(be1 + f + c2) - __ldg(mu1 + f + c2) * s;
        }
    }

    unsigned x_base = (unsigned)__cvta_generic_to_shared(x_s);
    unsigned h_base = (unsigned)__cvta_generic_to_shared(h_s);
    unsigned wW = (unsigned)__cvta_generic_to_shared(W_s);
    unsigned wU = (unsigned)__cvta_generic_to_shared(U_s);

    float2 creg[2][2];
    #pragma unroll
    for (int mt = 0; mt < 2; ++mt)
        #pragma unroll
        for (int r = 0; r < 2; ++r) { creg[mt][r].x = 0.f; creg[mt][r].y = 0.f; }

    for (int t = 0; t < NT; ++t) {
        const int frame = b * NT + t;

        float acc[2][4][4];
        #pragma unroll
        for (int mt = 0; mt < 2; ++mt)
            #pragma unroll
            for (int j = 0; j < 4; ++j)
                #pragma unroll
                for (int q = 0; q < 4; ++q) acc[mt][j][q] = 0.f;

        if (t > 0) {
            // h tile streams in while the x mainloop runs
            stage_tile_async(hstate + (size_t)b * (HWPX * 32), h_s, tid, y0);
            cpasync_commit();
            cpasync_wait1();          // x group (older) complete
        } else {
            cpasync_wait0();
        }

        // prefetch residual reads for this step (layer 1 only)
        float2 rpre[2][2];
        if (!IS_L0) {
            #pragma unroll
            for (int mt = 0; mt < 2; ++mt)
                #pragma unroll
                for (int r = 0; r < 2; ++r) {
                    int m = mwarp * 32 + mt * 16 + r * 8 + gid;
                    int pix = (y0 + (m >> 6)) * 64 + (m & 63);
                    rpre[mt][r] = __ldcg(reinterpret_cast<const float2*>(
                        res + ((size_t)frame * HWPX + pix) * 32 + f));
                }
        }

        __syncthreads();              // x_s visible block-wide
        conv_mainloop(x_base, wW, mwarp, nw, lane, acc);
        if (t > 0) {
            cpasync_wait0();          // h group complete
            __syncthreads();          // h_s visible block-wide
            conv_mainloop(h_base, wU, mwarp, nw, lane, acc);
        }

        #pragma unroll
        for (int mt = 0; mt < 2; ++mt) {
            #pragma unroll
            for (int r = 0; r < 2; ++r) {
                int m = mwarp * 32 + mt * 16 + r * 8 + gid;
                int xcol = m & 63;
                int pix = (y0 + (m >> 6)) * 64 + xcol;
                float z4[4][2];
                #pragma unroll
                for (int g = 0; g < 4; ++g) {
                    z4[g][0] = acc[mt][g][2 * r]     + bz[g][0];
                    z4[g][1] = acc[mt][g][2 * r + 1] + bz[g][1];
                }
                float2 cp = creg[mt][r];
                float2 cn, hv;
                cn.x = hsig(z4[1][0]) * cp.x + hsig(z4[0][0]) * tanhf(z4[2][0]);
                cn.y = hsig(z4[1][1]) * cp.y + hsig(z4[0][1]) * tanhf(z4[2][1]);
                hv.x = hsig(z4[3][0]) * tanhf(cn.x);
                hv.y = hsig(z4[3][1]) * tanhf(cn.y);
                creg[mt][r] = cn;
                int sch = (f >> 3) ^ (((xcol + 1) >> 1) & 3);
                if (t < NT - 1)
                    *reinterpret_cast<__half2*>(hstate + ((size_t)b * HWPX + pix) * 32
                                                + sch * 8 + (f & 7)) =
                        __floats2half2_rn(hv.x, hv.y);
                size_t oo = ((size_t)frame * HWPX + pix) * 32 + f;
                if (IS_L0) {
                    *reinterpret_cast<float2*>(out0 + oo) = hv;
                    *reinterpret_cast<__half2*>(out16 + ((size_t)frame * HWPX + pix) * 32
                                                + sch * 8 + (f & 7)) =
                        __floats2half2_rn(fmaf(hv.x, sbn[0], bbn[0]),
                                          fmaf(hv.y, sbn[1], bbn[1]));
                } else {
                    float2 ov; ov.x = hv.x + rpre[mt][r].x; ov.y = hv.y + rpre[mt][r].y;
                    *reinterpret_cast<float2*>(outF + oo) = ov;
                }
            }
        }

        if (t < NT - 1) {
            __syncthreads();     // all warps done reading x_s
            stage_tile_async(xin + (size_t)(frame + 1) * (HWPX * 32), x_s, tid, y0);
            cpasync_commit();    // overlaps with the barrier spin below
            grid_sync_b(b, bar_base + BBLK * (unsigned)(t + 1));
        }
    }
}

// ---------------------------------------------------------------------------
extern "C" void kernel_launch(void* const* d_in, const int* in_sizes, int n_in,
                              void* d_out, int out_size)
{
    (void)in_sizes; (void)n_in; (void)out_size;
    const float* x    = (const float*)d_in[0];
    const float* gma  = (const float*)d_in[1];
    const float* bta  = (const float*)d_in[2];
    const float* mu   = (const float*)d_in[3];
    const float* var  = (const float*)d_in[4];
    const float* ker  = (const float*)d_in[5];
    const float* rker = (const float*)d_in[6];
    const float* bias = (const float*)d_in[7];

    __half *xf16, *x2f16, *w16, *rw16, *h16;
    float *l0;
    cudaGetSymbolAddress((void**)&xf16,  g_xf16);
    cudaGetSymbolAddress((void**)&x2f16, g_x2f16);
    cudaGetSymbolAddress((void**)&w16,   g_w16);
    cudaGetSymbolAddress((void**)&rw16,  g_rw16);
    cudaGetSymbolAddress((void**)&h16,   g_h16);
    cudaGetSymbolAddress((void**)&l0,    g_l0);

    const size_t SMEM = (2 * 8448 + 2 * 18432) * sizeof(__half);   // 107520 B
    cudaFuncSetAttribute((const void*)lstm_fused<true>,
                         cudaFuncAttributeMaxDynamicSharedMemorySize, (int)SMEM);
    cudaFuncSetAttribute((const void*)lstm_fused<false>,
                         cudaFuncAttributeMaxDynamicSharedMemorySize, (int)SMEM);

    prep_all<<<4672, 256>>>(x, gma, bta, mu, var, ker, rker);

    float* outF = (float*)d_out;

    // ---- layer 0 ----
    lstm_fused<true><<<dim3(32, 2, NB), 256, SMEM>>>(
        xf16, w16, rw16, bias, h16, l0, x2f16, nullptr, nullptr,
        gma + 32, bta + 32, mu + 32, var + 32, 0u);

    // ---- layer 1 ----
    lstm_fused<false><<<dim3(32, 2, NB), 256, SMEM>>>(
        x2f16, w16 + 2 * WHALF, rw16 + 2 * WHALF, bias + 128, h16,
        nullptr, nullptr, l0, outF,
        nullptr, nullptr, nullptr, nullptr, BBLK * (NT - 1));
}